// round 4
// baseline (speedup 1.0000x reference)
#include <cuda_runtime.h>
#include <cuda_bf16.h>
#include <math.h>

// Problem constants
#define B_ 2
#define T_ 2048
#define C_ 1024
#define H_ 8
#define D_ 1024
#define V_ 32000
#define HD_ (H_*D_)
#define FF_ (4*C_)

// Scratch (device globals; no dynamic allocation allowed)
__device__ float g_x  [B_*T_*C_];
__device__ float g_h  [B_*T_*C_];
__device__ float g_q  [B_*H_*T_*D_];
__device__ float g_k  [B_*H_*T_*D_];
__device__ float g_v  [B_*H_*T_*D_];
__device__ float g_att[B_*T_*HD_];
__device__ float g_ffn[B_*T_*FF_];
__device__ float g_wei[(size_t)B_*H_*T_*T_];
// tf32-rounded weight copies
__device__ float g_cWq [H_*C_*D_];
__device__ float g_cWk [H_*C_*D_];
__device__ float g_cWv [H_*C_*D_];
__device__ float g_cWo [HD_*C_];
__device__ float g_cW1 [C_*FF_];
__device__ float g_cW2 [FF_*C_];
__device__ float g_cWlm[C_*V_];

#define F_BIAS    1
#define F_ADDC    2
#define F_RELU    4
#define F_CAUSALK 8
#define F_TF32    16

__device__ __forceinline__ float tf32r(float x) {
    unsigned r;
    asm("cvt.rna.tf32.f32 %0, %1;" : "=r"(r) : "f"(x));
    return __uint_as_float(r);
}

// ---------------------------------------------------------------------------
// Weight pre-rounding (float4 grid-stride)
// ---------------------------------------------------------------------------
__global__ void cvt_tf32_kernel(const float4* __restrict__ in, float4* __restrict__ out, int n4) {
    int i = blockIdx.x * blockDim.x + threadIdx.x;
    if (i < n4) {
        float4 v = in[i];
        v.x = tf32r(v.x); v.y = tf32r(v.y); v.z = tf32r(v.z); v.w = tf32r(v.w);
        out[i] = v;
    }
}

// ---------------------------------------------------------------------------
// Embedding
// ---------------------------------------------------------------------------
__global__ void embed_kernel(const int* __restrict__ idx,
                             const float* __restrict__ tok,
                             const float* __restrict__ pos) {
    int i = blockIdx.x * blockDim.x + threadIdx.x;
    int c  = i % C_;
    int bt = i / C_;
    int t  = bt % T_;
    g_x[i] = tok[(size_t)idx[bt] * C_ + c] + pos[t * C_ + c];
}

// ---------------------------------------------------------------------------
// LayerNorm (C=1024); output rounded to tf32 (always feeds a GEMM A operand)
// ---------------------------------------------------------------------------
__global__ void ln_kernel(const float* __restrict__ in, float* __restrict__ out,
                          const float* __restrict__ g, const float* __restrict__ b) {
    int row = blockIdx.x;
    const float* x = in + (size_t)row * C_;
    float* o = out + (size_t)row * C_;
    int tid = threadIdx.x;

    __shared__ float rs[256], rss[256];
    float s = 0.f, ss = 0.f;
    for (int c = tid; c < C_; c += 256) { float v = x[c]; s += v; ss += v * v; }
    rs[tid] = s; rss[tid] = ss;
    __syncthreads();
    for (int off = 128; off > 0; off >>= 1) {
        if (tid < off) { rs[tid] += rs[tid + off]; rss[tid] += rss[tid + off]; }
        __syncthreads();
    }
    float mean = rs[0] * (1.0f / C_);
    float var  = rss[0] * (1.0f / C_) - mean * mean;
    float inv  = rsqrtf(var + 1e-5f);
    for (int c = tid; c < C_; c += 256)
        o[c] = tf32r((x[c] - mean) * inv * g[c] + b[c]);
}

// ---------------------------------------------------------------------------
// Causal softmax; probs rounded to tf32; zero pad up to next 128 boundary
// ---------------------------------------------------------------------------
__global__ void softmax_kernel(float* __restrict__ wei) {
    int row = blockIdx.x;
    int t = row % T_;
    float* w = wei + (size_t)row * T_;
    int n = t + 1;
    int tid = threadIdx.x;
    __shared__ float red[256];

    float m = -1e30f;
    for (int s = tid; s < n; s += 256) m = fmaxf(m, w[s]);
    red[tid] = m;
    __syncthreads();
    for (int off = 128; off > 0; off >>= 1) {
        if (tid < off) red[tid] = fmaxf(red[tid], red[tid + off]);
        __syncthreads();
    }
    m = red[0];
    __syncthreads();

    float sum = 0.f;
    for (int s = tid; s < n; s += 256) { float e = expf(w[s] - m); w[s] = e; sum += e; }
    red[tid] = sum;
    __syncthreads();
    for (int off = 128; off > 0; off >>= 1) {
        if (tid < off) red[tid] += red[tid + off];
        __syncthreads();
    }
    float inv = 1.f / red[0];
    for (int s = tid; s < n; s += 256) w[s] = tf32r(w[s] * inv);

    int nend = (n + 127) & ~127;
    for (int s = n + tid; s < nend; s += 256) w[s] = 0.f;
}

// ---------------------------------------------------------------------------
// mma helpers (operands already in tf32 bit format — no cvt in loop)
// ---------------------------------------------------------------------------
__device__ __forceinline__ void mma8(float* d, const unsigned* a, unsigned b0, unsigned b1) {
    asm volatile(
        "mma.sync.aligned.m16n8k8.row.col.f32.tf32.tf32.f32 "
        "{%0,%1,%2,%3}, {%4,%5,%6,%7}, {%8,%9}, {%0,%1,%2,%3};\n"
        : "+f"(d[0]), "+f"(d[1]), "+f"(d[2]), "+f"(d[3])
        : "r"(a[0]), "r"(a[1]), "r"(a[2]), "r"(a[3]), "r"(b0), "r"(b1));
}

__device__ __forceinline__ void cp16(void* s, const void* g) {
    unsigned sa = (unsigned)__cvta_generic_to_shared(s);
    asm volatile("cp.async.cg.shared.global [%0], [%1], 16;\n" :: "r"(sa), "l"(g));
}
__device__ __forceinline__ void cp_commit() {
    asm volatile("cp.async.commit_group;\n" ::);
}
__device__ __forceinline__ unsigned ldu(const float* p) {
    return __float_as_uint(*p);
}

// A-style tile: [128 rows][k, stride 20]  (banks 20g+tig -> conflict-free)
// B-style tile: [16 k-rows][col, stride 136] (banks 8tig+g -> conflict-free)
#define AP 20
#define BP 136

// Warp tile 64x32: 4 m-subtiles x 4 n-subtiles
__device__ __forceinline__ void compute_k8_nn(
    const float (* __restrict__ As)[AP], const float (* __restrict__ Bs)[BP],
    float acc[4][4][4], int kk, int wm, int wn, int g, int tig)
{
    unsigned a[4][4];
#pragma unroll
    for (int mt = 0; mt < 4; mt++) {
        int mrow = wm * 64 + mt * 16;
        a[mt][0] = ldu(&As[mrow + g    ][kk + tig    ]);
        a[mt][1] = ldu(&As[mrow + g + 8][kk + tig    ]);
        a[mt][2] = ldu(&As[mrow + g    ][kk + tig + 4]);
        a[mt][3] = ldu(&As[mrow + g + 8][kk + tig + 4]);
    }
#pragma unroll
    for (int nt = 0; nt < 4; nt++) {
        int ncol = wn * 32 + nt * 8 + g;
        unsigned b0 = ldu(&Bs[kk + tig    ][ncol]);
        unsigned b1 = ldu(&Bs[kk + tig + 4][ncol]);
#pragma unroll
        for (int mt = 0; mt < 4; mt++) mma8(acc[mt][nt], a[mt], b0, b1);
    }
}

__device__ __forceinline__ void compute_k8_nt(
    const float (* __restrict__ As)[AP], const float (* __restrict__ Bt)[AP],
    float acc[4][4][4], int kk, int wm, int wn, int g, int tig)
{
    unsigned a[4][4];
#pragma unroll
    for (int mt = 0; mt < 4; mt++) {
        int mrow = wm * 64 + mt * 16;
        a[mt][0] = ldu(&As[mrow + g    ][kk + tig    ]);
        a[mt][1] = ldu(&As[mrow + g + 8][kk + tig    ]);
        a[mt][2] = ldu(&As[mrow + g    ][kk + tig + 4]);
        a[mt][3] = ldu(&As[mrow + g + 8][kk + tig + 4]);
    }
#pragma unroll
    for (int nt = 0; nt < 4; nt++) {
        int ncol = wn * 32 + nt * 8 + g;
        unsigned b0 = ldu(&Bt[ncol][kk + tig    ]);
        unsigned b1 = ldu(&Bt[ncol][kk + tig + 4]);
#pragma unroll
        for (int mt = 0; mt < 4; mt++) mma8(acc[mt][nt], a[mt], b0, b1);
    }
}

// ---------------------------------------------------------------------------
// tf32 GEMM NN: 128x128 tile, BK=16, 256 threads (8 warps of 64x32)
// ---------------------------------------------------------------------------
__global__ void __launch_bounds__(256, 2)
mma_nn(const float* __restrict__ A, const float* __restrict__ Bm,
       float* __restrict__ Cm,
       int K, int lda, int ldb, int ldc,
       long sAb, long sAh, long sBb, long sBh, long sCb, long sCh, int batchH,
       const float* __restrict__ bias, float scale, int flags)
{
    __shared__ float As[2][128][AP];
    __shared__ float Bs[2][16][BP];

    int z  = blockIdx.z;
    int zb = z / batchH, zh = z % batchH;
    A  += zb * sAb + zh * sAh;
    Bm += zb * sBb + zh * sBh;
    Cm += zb * sCb + zh * sCh;

    int bx = blockIdx.x, by = blockIdx.y;
    int row0 = by * 128, col0 = bx * 128;

    int Keff = K;
    if (flags & F_CAUSALK) { int kl = (by + 1) * 128; if (kl < Keff) Keff = kl; }

    int tid  = threadIdx.x;
    int lane = tid & 31, warp = tid >> 5;
    int wm = warp >> 2, wn = warp & 3;      // 2 x 4 warp grid
    int g  = lane >> 2, tig = lane & 3;

    const float* Ag = A  + (size_t)row0 * lda;
    const float* Bg = Bm + col0;
    int arow = tid >> 2, ac = (tid & 3) * 4;   // A: 64 rows x 16k per pass, 2 passes
    int brow = tid >> 5, bc = (tid & 31) * 4;  // B: 8 k-rows x 128 cols per pass, 2 passes

    float acc[4][4][4];
#pragma unroll
    for (int i = 0; i < 4; i++)
#pragma unroll
        for (int j = 0; j < 4; j++)
#pragma unroll
            for (int r = 0; r < 4; r++) acc[i][j][r] = 0.f;

    int iters = Keff / 16;

    {
#pragma unroll
        for (int p = 0; p < 2; p++)
            cp16(&As[0][arow + 64 * p][ac], Ag + (size_t)(arow + 64 * p) * lda + ac);
#pragma unroll
        for (int p = 0; p < 2; p++)
            cp16(&Bs[0][brow + 8 * p][bc], Bg + (size_t)(brow + 8 * p) * ldb + bc);
        cp_commit();
    }

    int cur = 0;
    for (int it = 0; it < iters; ++it) {
        bool hn = (it + 1 < iters);
        if (hn) {
            int k0 = (it + 1) * 16;
            int nxt = cur ^ 1;
#pragma unroll
            for (int p = 0; p < 2; p++)
                cp16(&As[nxt][arow + 64 * p][ac], Ag + (size_t)(arow + 64 * p) * lda + k0 + ac);
#pragma unroll
            for (int p = 0; p < 2; p++)
                cp16(&Bs[nxt][brow + 8 * p][bc], Bg + (size_t)(k0 + brow + 8 * p) * ldb + bc);
            cp_commit();
            asm volatile("cp.async.wait_group 1;\n" ::);
        } else {
            asm volatile("cp.async.wait_group 0;\n" ::);
        }
        __syncthreads();
        compute_k8_nn(As[cur], Bs[cur], acc, 0, wm, wn, g, tig);
        compute_k8_nn(As[cur], Bs[cur], acc, 8, wm, wn, g, tig);
        __syncthreads();
        cur ^= 1;
    }

#pragma unroll
    for (int mt = 0; mt < 4; mt++) {
#pragma unroll
        for (int nt = 0; nt < 4; nt++) {
            int r = row0 + wm * 64 + mt * 16 + g;
            int c = col0 + wn * 32 + nt * 8 + tig * 2;
#pragma unroll
            for (int half = 0; half < 2; half++) {
                float* p = Cm + (size_t)(r + 8 * half) * ldc + c;
                float x0 = acc[mt][nt][2*half + 0] * scale;
                float x1 = acc[mt][nt][2*half + 1] * scale;
                if (flags & F_BIAS) { x0 += bias[c]; x1 += bias[c + 1]; }
                if (flags & F_RELU) { x0 = fmaxf(x0, 0.f); x1 = fmaxf(x1, 0.f); }
                if (flags & F_TF32) { x0 = tf32r(x0); x1 = tf32r(x1); }
                if (flags & F_ADDC) { x0 += p[0]; x1 += p[1]; }
                p[0] = x0; p[1] = x1;
            }
        }
    }
}

// ---------------------------------------------------------------------------
// tf32 GEMM NT (scores): C = scale * A[M,K] @ B[N,K]^T, causal tile skip
// ---------------------------------------------------------------------------
__global__ void __launch_bounds__(256, 2)
mma_nt_scores(const float* __restrict__ A, const float* __restrict__ Bm,
              float* __restrict__ Cm,
              int K, int lda, int ldb, int ldc,
              long sA, long sB, long sC, float scale)
{
    int bx = blockIdx.x, by = blockIdx.y;
    if (bx > by) return;

    __shared__ float As[2][128][AP];
    __shared__ float Bt[2][128][AP];

    int z = blockIdx.z;
    A  += (long)z * sA;
    Bm += (long)z * sB;
    Cm += (long)z * sC;

    int row0 = by * 128, col0 = bx * 128;

    int tid  = threadIdx.x;
    int lane = tid & 31, warp = tid >> 5;
    int wm = warp >> 2, wn = warp & 3;
    int g  = lane >> 2, tig = lane & 3;

    const float* Ag = A  + (size_t)row0 * lda;
    const float* Bg = Bm + (size_t)col0 * ldb;
    int arow = tid >> 2, ac = (tid & 3) * 4;

    float acc[4][4][4];
#pragma unroll
    for (int i = 0; i < 4; i++)
#pragma unroll
        for (int j = 0; j < 4; j++)
#pragma unroll
            for (int r = 0; r < 4; r++) acc[i][j][r] = 0.f;

    int iters = K / 16;

    {
#pragma unroll
        for (int p = 0; p < 2; p++)
            cp16(&As[0][arow + 64 * p][ac], Ag + (size_t)(arow + 64 * p) * lda + ac);
#pragma unroll
        for (int p = 0; p < 2; p++)
            cp16(&Bt[0][arow + 64 * p][ac], Bg + (size_t)(arow + 64 * p) * ldb + ac);
        cp_commit();
    }

    int cur = 0;
    for (int it = 0; it < iters; ++it) {
        bool hn = (it + 1 < iters);
        if (hn) {
            int k0 = (it + 1) * 16;
            int nxt = cur ^ 1;
#pragma unroll
            for (int p = 0; p < 2; p++)
                cp16(&As[nxt][arow + 64 * p][ac], Ag + (size_t)(arow + 64 * p) * lda + k0 + ac);
#pragma unroll
            for (int p = 0; p < 2; p++)
                cp16(&Bt[nxt][arow + 64 * p][ac], Bg + (size_t)(arow + 64 * p) * ldb + k0 + ac);
            cp_commit();
            asm volatile("cp.async.wait_group 1;\n" ::);
        } else {
            asm volatile("cp.async.wait_group 0;\n" ::);
        }
        __syncthreads();
        compute_k8_nt(As[cur], Bt[cur], acc, 0, wm, wn, g, tig);
        compute_k8_nt(As[cur], Bt[cur], acc, 8, wm, wn, g, tig);
        __syncthreads();
        cur ^= 1;
    }

#pragma unroll
    for (int mt = 0; mt < 4; mt++) {
#pragma unroll
        for (int nt = 0; nt < 4; nt++) {
            int r = row0 + wm * 64 + mt * 16 + g;
            int c = col0 + wn * 32 + nt * 8 + tig * 2;
#pragma unroll
            for (int half = 0; half < 2; half++) {
                float* p = Cm + (size_t)(r + 8 * half) * ldc + c;
                p[0] = acc[mt][nt][2*half + 0] * scale;
                p[1] = acc[mt][nt][2*half + 1] * scale;
            }
        }
    }
}

// ---------------------------------------------------------------------------
// Host launch
// ---------------------------------------------------------------------------
extern "C" void kernel_launch(void* const* d_in, const int* in_sizes, int n_in,
                              void* d_out, int out_size) {
    const int*   idx = (const int*)  d_in[0];
    const float* tok = (const float*)d_in[1];
    const float* pos = (const float*)d_in[2];
    const float* Wq  = (const float*)d_in[3];
    const float* Wk  = (const float*)d_in[4];
    const float* Wv  = (const float*)d_in[5];
    const float* Wo  = (const float*)d_in[6];
    const float* bo  = (const float*)d_in[7];
    const float* W1  = (const float*)d_in[8];
    const float* b1  = (const float*)d_in[9];
    const float* W2  = (const float*)d_in[10];
    const float* b2  = (const float*)d_in[11];
    const float* g1  = (const float*)d_in[12];
    const float* be1 = (const float*)d_in[13];
    const float* g2  = (const float*)d_in[14];
    const float* be2 = (const float*)d_in[15];
    const float* gf  = (const float*)d_in[16];
    const float* bef = (const float*)d_in[17];
    const float* Wlm = (const float*)d_in[18];
    const float* blm = (const float*)d_in[19];
    float* out = (float*)d_out;

    float *x, *h, *q, *k, *v, *att, *ffn, *wei;
    float *cWq, *cWk, *cWv, *cWo, *cW1, *cW2, *cWlm;
    cudaGetSymbolAddress((void**)&x,   g_x);
    cudaGetSymbolAddress((void**)&h,   g_h);
    cudaGetSymbolAddress((void**)&q,   g_q);
    cudaGetSymbolAddress((void**)&k,   g_k);
    cudaGetSymbolAddress((void**)&v,   g_v);
    cudaGetSymbolAddress((void**)&att, g_att);
    cudaGetSymbolAddress((void**)&ffn, g_ffn);
    cudaGetSymbolAddress((void**)&wei, g_wei);
    cudaGetSymbolAddress((void**)&cWq, g_cWq);
    cudaGetSymbolAddress((void**)&cWk, g_cWk);
    cudaGetSymbolAddress((void**)&cWv, g_cWv);
    cudaGetSymbolAddress((void**)&cWo, g_cWo);
    cudaGetSymbolAddress((void**)&cW1, g_cW1);
    cudaGetSymbolAddress((void**)&cW2, g_cW2);
    cudaGetSymbolAddress((void**)&cWlm, g_cWlm);

    // 0. pre-round weights to tf32 format
    {
        auto cvt = [](const float* in, float* outp, long n) {
            int n4 = (int)(n / 4);
            cvt_tf32_kernel<<<(n4 + 255) / 256, 256>>>((const float4*)in, (float4*)outp, n4);
        };
        cvt(Wq, cWq, (long)H_*C_*D_);
        cvt(Wk, cWk, (long)H_*C_*D_);
        cvt(Wv, cWv, (long)H_*C_*D_);
        cvt(Wo, cWo, (long)HD_*C_);
        cvt(W1, cW1, (long)C_*FF_);
        cvt(W2, cW2, (long)FF_*C_);
        cvt(Wlm, cWlm, (long)C_*V_);
    }

    // 1. embedding
    embed_kernel<<<(B_*T_*C_)/256, 256>>>(idx, tok, pos);

    // 2. LN1 (tf32-rounded output)
    ln_kernel<<<B_*T_, 256>>>(x, h, g1, be1);

    // 3. q,k,v projections (outputs rounded)
    {
        dim3 grid(D_/128, T_/128, B_*H_);
        long sAb = (long)T_*C_, sBh = (long)C_*D_;
        long sCb = (long)H_*T_*D_, sCh = (long)T_*D_;
        mma_nn<<<grid, 256>>>(h, cWq, q, C_, C_, D_, D_,
                              sAb, 0, 0, sBh, sCb, sCh, H_, nullptr, 1.f, F_TF32);
        mma_nn<<<grid, 256>>>(h, cWk, k, C_, C_, D_, D_,
                              sAb, 0, 0, sBh, sCb, sCh, H_, nullptr, 1.f, F_TF32);
        mma_nn<<<grid, 256>>>(h, cWv, v, C_, C_, D_, D_,
                              sAb, 0, 0, sBh, sCb, sCh, H_, nullptr, 1.f, F_TF32);
    }

    // 4. scores
    {
        dim3 grid(T_/128, T_/128, B_*H_);
        mma_nt_scores<<<grid, 256>>>(q, k, wei, D_, D_, D_, T_,
                                     (long)T_*D_, (long)T_*D_, (long)T_*T_,
                                     rsqrtf((float)D_));
    }

    // 5. softmax (tf32-rounded probs)
    softmax_kernel<<<B_*H_*T_, 256>>>(wei);

    // 6. att = wei @ v  ([B,T,H*D] layout, causal K-limit, rounded output)
    {
        dim3 grid(D_/128, T_/128, B_*H_);
        mma_nn<<<grid, 256>>>(wei, v, att, T_, T_, D_, HD_,
                              (long)H_*T_*T_, (long)T_*T_,
                              (long)H_*T_*D_, (long)T_*D_,
                              (long)T_*HD_, (long)D_, H_,
                              nullptr, 1.f, F_CAUSALK | F_TF32);
    }

    // 7. x += att @ Wo + bo
    mma_nn<<<dim3(C_/128, (B_*T_)/128, 1), 256>>>(
        att, cWo, x, HD_, HD_, C_, C_,
        0, 0, 0, 0, 0, 0, 1, bo, 1.f, F_BIAS | F_ADDC);

    // 8. LN2
    ln_kernel<<<B_*T_, 256>>>(x, h, g2, be2);

    // 9. ffn = relu(h @ W1 + b1)  (rounded output)
    mma_nn<<<dim3(FF_/128, (B_*T_)/128, 1), 256>>>(
        h, cW1, ffn, C_, C_, FF_, FF_,
        0, 0, 0, 0, 0, 0, 1, b1, 1.f, F_BIAS | F_RELU | F_TF32);

    // 10. x += ffn @ W2 + b2
    mma_nn<<<dim3(C_/128, (B_*T_)/128, 1), 256>>>(
        ffn, cW2, x, FF_, FF_, C_, C_,
        0, 0, 0, 0, 0, 0, 1, b2, 1.f, F_BIAS | F_ADDC);

    // 11. final LN
    ln_kernel<<<B_*T_, 256>>>(x, h, gf, bef);

    // 12. logits = h @ Wlm + blm
    mma_nn<<<dim3(V_/128, (B_*T_)/128, 1), 256>>>(
        h, cWlm, out, C_, C_, V_, V_,
        0, 0, 0, 0, 0, 0, 1, blm, 1.f, F_BIAS);
}

// round 6
// speedup vs baseline: 1.0517x; 1.0517x over previous
#include <cuda_runtime.h>
#include <cuda_bf16.h>
#include <math.h>

// Problem constants
#define B_ 2
#define T_ 2048
#define C_ 1024
#define H_ 8
#define D_ 1024
#define V_ 32000
#define HD_ (H_*D_)
#define FF_ (4*C_)

// Scratch (device globals; no dynamic allocation allowed)
__device__ float g_x  [B_*T_*C_];
__device__ float g_h  [B_*T_*C_];
__device__ float g_q  [B_*H_*T_*D_];
__device__ float g_k  [B_*H_*T_*D_];
__device__ float g_v  [B_*H_*T_*D_];
__device__ float g_att[B_*T_*HD_];
__device__ float g_ffn[B_*T_*FF_];
__device__ float g_wei[(size_t)B_*H_*T_*T_];
// tf32-rounded weight copies
__device__ float g_cWq [H_*C_*D_];
__device__ float g_cWk [H_*C_*D_];
__device__ float g_cWv [H_*C_*D_];
__device__ float g_cWo [HD_*C_];
__device__ float g_cW1 [C_*FF_];
__device__ float g_cW2 [FF_*C_];
__device__ float g_cWlm[C_*V_];

#define F_BIAS    1
#define F_ADDC    2
#define F_RELU    4
#define F_CAUSALK 8
#define F_TF32    16

__device__ __forceinline__ float tf32r(float x) {
    unsigned r;
    asm("cvt.rna.tf32.f32 %0, %1;" : "=r"(r) : "f"(x));
    return __uint_as_float(r);
}

// ---------------------------------------------------------------------------
// Weight pre-rounding (float4)
// ---------------------------------------------------------------------------
__global__ void cvt_tf32_kernel(const float4* __restrict__ in, float4* __restrict__ out, int n4) {
    int i = blockIdx.x * blockDim.x + threadIdx.x;
    if (i < n4) {
        float4 v = in[i];
        v.x = tf32r(v.x); v.y = tf32r(v.y); v.z = tf32r(v.z); v.w = tf32r(v.w);
        out[i] = v;
    }
}

// ---------------------------------------------------------------------------
// Embedding
// ---------------------------------------------------------------------------
__global__ void embed_kernel(const int* __restrict__ idx,
                             const float* __restrict__ tok,
                             const float* __restrict__ pos) {
    int i = blockIdx.x * blockDim.x + threadIdx.x;
    int c  = i % C_;
    int bt = i / C_;
    int t  = bt % T_;
    g_x[i] = tok[(size_t)idx[bt] * C_ + c] + pos[t * C_ + c];
}

// ---------------------------------------------------------------------------
// LayerNorm (C=1024); output rounded to tf32 (feeds GEMM A operands)
// ---------------------------------------------------------------------------
__global__ void ln_kernel(const float* __restrict__ in, float* __restrict__ out,
                          const float* __restrict__ g, const float* __restrict__ b) {
    int row = blockIdx.x;
    const float* x = in + (size_t)row * C_;
    float* o = out + (size_t)row * C_;
    int tid = threadIdx.x;

    __shared__ float rs[256], rss[256];
    float s = 0.f, ss = 0.f;
    for (int c = tid; c < C_; c += 256) { float v = x[c]; s += v; ss += v * v; }
    rs[tid] = s; rss[tid] = ss;
    __syncthreads();
    for (int off = 128; off > 0; off >>= 1) {
        if (tid < off) { rs[tid] += rs[tid + off]; rss[tid] += rss[tid + off]; }
        __syncthreads();
    }
    float mean = rs[0] * (1.0f / C_);
    float var  = rss[0] * (1.0f / C_) - mean * mean;
    float inv  = rsqrtf(var + 1e-5f);
    for (int c = tid; c < C_; c += 256)
        o[c] = tf32r((x[c] - mean) * inv * g[c] + b[c]);
}

// ---------------------------------------------------------------------------
// Causal softmax; probs tf32-rounded; zero pad up to next 128 boundary
// ---------------------------------------------------------------------------
__global__ void softmax_kernel(float* __restrict__ wei) {
    int row = blockIdx.x;
    int t = row % T_;
    float* w = wei + (size_t)row * T_;
    int n = t + 1;
    int tid = threadIdx.x;
    __shared__ float red[256];

    float m = -1e30f;
    for (int s = tid; s < n; s += 256) m = fmaxf(m, w[s]);
    red[tid] = m;
    __syncthreads();
    for (int off = 128; off > 0; off >>= 1) {
        if (tid < off) red[tid] = fmaxf(red[tid], red[tid + off]);
        __syncthreads();
    }
    m = red[0];
    __syncthreads();

    float sum = 0.f;
    for (int s = tid; s < n; s += 256) { float e = expf(w[s] - m); w[s] = e; sum += e; }
    red[tid] = sum;
    __syncthreads();
    for (int off = 128; off > 0; off >>= 1) {
        if (tid < off) red[tid] += red[tid + off];
        __syncthreads();
    }
    float inv = 1.f / red[0];
    for (int s = tid; s < n; s += 256) w[s] = tf32r(w[s] * inv);

    int nend = (n + 127) & ~127;
    for (int s = n + tid; s < nend; s += 256) w[s] = 0.f;
}

// ---------------------------------------------------------------------------
// mma helpers (operands already tf32-formatted — no cvt in loop)
// ---------------------------------------------------------------------------
__device__ __forceinline__ void mma8(float* d, const unsigned* a, unsigned b0, unsigned b1) {
    asm volatile(
        "mma.sync.aligned.m16n8k8.row.col.f32.tf32.tf32.f32 "
        "{%0,%1,%2,%3}, {%4,%5,%6,%7}, {%8,%9}, {%0,%1,%2,%3};\n"
        : "+f"(d[0]), "+f"(d[1]), "+f"(d[2]), "+f"(d[3])
        : "r"(a[0]), "r"(a[1]), "r"(a[2]), "r"(a[3]), "r"(b0), "r"(b1));
}

__device__ __forceinline__ void cp16(void* s, const void* g) {
    unsigned sa = (unsigned)__cvta_generic_to_shared(s);
    asm volatile("cp.async.cg.shared.global [%0], [%1], 16;\n" :: "r"(sa), "l"(g));
}
__device__ __forceinline__ void cp_commit() {
    asm volatile("cp.async.commit_group;\n" ::);
}
__device__ __forceinline__ unsigned ldu(const float* p) {
    return __float_as_uint(*p);
}

// A-style tile: [128 rows][k, stride 20]  (banks 20g+tig -> conflict-free)
// B-style tile: [16 k-rows][col, stride 136] (banks 8tig+g -> conflict-free)
#define AP 20
#define BP 136

// Warp tile 64x64: 4 m-subtiles x 8 n-subtiles (round-3 shape)
__device__ __forceinline__ void compute_k8_nn(
    const float (* __restrict__ As)[AP], const float (* __restrict__ Bs)[BP],
    float acc[4][8][4], int kk, int wm, int wn, int g, int tig)
{
    unsigned a[4][4];
#pragma unroll
    for (int mt = 0; mt < 4; mt++) {
        int mrow = wm * 64 + mt * 16;
        a[mt][0] = ldu(&As[mrow + g    ][kk + tig    ]);
        a[mt][1] = ldu(&As[mrow + g + 8][kk + tig    ]);
        a[mt][2] = ldu(&As[mrow + g    ][kk + tig + 4]);
        a[mt][3] = ldu(&As[mrow + g + 8][kk + tig + 4]);
    }
#pragma unroll
    for (int nt = 0; nt < 8; nt++) {
        int ncol = wn * 64 + nt * 8 + g;
        unsigned b0 = ldu(&Bs[kk + tig    ][ncol]);
        unsigned b1 = ldu(&Bs[kk + tig + 4][ncol]);
#pragma unroll
        for (int mt = 0; mt < 4; mt++) mma8(acc[mt][nt], a[mt], b0, b1);
    }
}

__device__ __forceinline__ void compute_k8_nt(
    const float (* __restrict__ As)[AP], const float (* __restrict__ Bt)[AP],
    float acc[4][8][4], int kk, int wm, int wn, int g, int tig)
{
    unsigned a[4][4];
#pragma unroll
    for (int mt = 0; mt < 4; mt++) {
        int mrow = wm * 64 + mt * 16;
        a[mt][0] = ldu(&As[mrow + g    ][kk + tig    ]);
        a[mt][1] = ldu(&As[mrow + g + 8][kk + tig    ]);
        a[mt][2] = ldu(&As[mrow + g    ][kk + tig + 4]);
        a[mt][3] = ldu(&As[mrow + g + 8][kk + tig + 4]);
    }
#pragma unroll
    for (int nt = 0; nt < 8; nt++) {
        int ncol = wn * 64 + nt * 8 + g;
        unsigned b0 = ldu(&Bt[ncol][kk + tig    ]);
        unsigned b1 = ldu(&Bt[ncol][kk + tig + 4]);
#pragma unroll
        for (int mt = 0; mt < 4; mt++) mma8(acc[mt][nt], a[mt], b0, b1);
    }
}

// ---------------------------------------------------------------------------
// tf32 GEMM NN: 128x128 tile, BK=16, 128 threads (4 warps of 64x64), cp.async
// ---------------------------------------------------------------------------
__global__ void __launch_bounds__(128, 3)
mma_nn(const float* __restrict__ A, const float* __restrict__ Bm,
       float* __restrict__ Cm,
       int K, int lda, int ldb, int ldc,
       long sAb, long sAh, long sBb, long sBh, long sCb, long sCh, int batchH,
       const float* __restrict__ bias, float scale, int flags)
{
    __shared__ float As[2][128][AP];
    __shared__ float Bs[2][16][BP];

    int z  = blockIdx.z;
    int zb = z / batchH, zh = z % batchH;
    A  += zb * sAb + zh * sAh;
    Bm += zb * sBb + zh * sBh;
    Cm += zb * sCb + zh * sCh;

    int bx = blockIdx.x, by = blockIdx.y;
    int row0 = by * 128, col0 = bx * 128;

    int Keff = K;
    if (flags & F_CAUSALK) { int kl = (by + 1) * 128; if (kl < Keff) Keff = kl; }

    int tid  = threadIdx.x;
    int lane = tid & 31, warp = tid >> 5;
    int wm = warp >> 1, wn = warp & 1;
    int g  = lane >> 2, tig = lane & 3;

    const float* Ag = A  + (size_t)row0 * lda;
    const float* Bg = Bm + col0;
    int arow = tid >> 2, ac = (tid & 3) * 4;   // A: 32 rows x 16k per pass
    int brow = tid >> 5, bc = (tid & 31) * 4;  // B: 4 k-rows x 128 cols per pass

    float acc[4][8][4];
#pragma unroll
    for (int i = 0; i < 4; i++)
#pragma unroll
        for (int j = 0; j < 8; j++)
#pragma unroll
            for (int r = 0; r < 4; r++) acc[i][j][r] = 0.f;

    int iters = Keff / 16;

    // prologue: stage 0
    {
#pragma unroll
        for (int p = 0; p < 4; p++)
            cp16(&As[0][arow + 32 * p][ac], Ag + (size_t)(arow + 32 * p) * lda + ac);
#pragma unroll
        for (int p = 0; p < 4; p++)
            cp16(&Bs[0][brow + 4 * p][bc], Bg + (size_t)(brow + 4 * p) * ldb + bc);
        cp_commit();
    }

    int cur = 0;
    for (int it = 0; it < iters; ++it) {
        bool hn = (it + 1 < iters);
        if (hn) {
            int k0 = (it + 1) * 16;
            int nxt = cur ^ 1;
#pragma unroll
            for (int p = 0; p < 4; p++)
                cp16(&As[nxt][arow + 32 * p][ac], Ag + (size_t)(arow + 32 * p) * lda + k0 + ac);
#pragma unroll
            for (int p = 0; p < 4; p++)
                cp16(&Bs[nxt][brow + 4 * p][bc], Bg + (size_t)(k0 + brow + 4 * p) * ldb + bc);
            cp_commit();
            asm volatile("cp.async.wait_group 1;\n" ::);
        } else {
            asm volatile("cp.async.wait_group 0;\n" ::);
        }
        __syncthreads();
        compute_k8_nn(As[cur], Bs[cur], acc, 0, wm, wn, g, tig);
        compute_k8_nn(As[cur], Bs[cur], acc, 8, wm, wn, g, tig);
        __syncthreads();
        cur ^= 1;
    }

    // epilogue
#pragma unroll
    for (int mt = 0; mt < 4; mt++) {
#pragma unroll
        for (int nt = 0; nt < 8; nt++) {
            int r = row0 + wm * 64 + mt * 16 + g;
            int c = col0 + wn * 64 + nt * 8 + tig * 2;
#pragma unroll
            for (int half = 0; half < 2; half++) {
                float* p = Cm + (size_t)(r + 8 * half) * ldc + c;
                float x0 = acc[mt][nt][2*half + 0] * scale;
                float x1 = acc[mt][nt][2*half + 1] * scale;
                if (flags & F_BIAS) { x0 += bias[c]; x1 += bias[c + 1]; }
                if (flags & F_RELU) { x0 = fmaxf(x0, 0.f); x1 = fmaxf(x1, 0.f); }
                if (flags & F_TF32) { x0 = tf32r(x0); x1 = tf32r(x1); }
                if (flags & F_ADDC) { x0 += p[0]; x1 += p[1]; }
                p[0] = x0; p[1] = x1;
            }
        }
    }
}

// ---------------------------------------------------------------------------
// tf32 GEMM NT (scores): C = scale * A[M,K] @ B[N,K]^T, causal tile skip
// ---------------------------------------------------------------------------
__global__ void __launch_bounds__(128, 3)
mma_nt_scores(const float* __restrict__ A, const float* __restrict__ Bm,
              float* __restrict__ Cm,
              int K, int lda, int ldb, int ldc,
              long sA, long sB, long sC, float scale)
{
    int bx = blockIdx.x, by = blockIdx.y;
    if (bx > by) return;

    __shared__ float As[2][128][AP];
    __shared__ float Bt[2][128][AP];

    int z = blockIdx.z;
    A  += (long)z * sA;
    Bm += (long)z * sB;
    Cm += (long)z * sC;

    int row0 = by * 128, col0 = bx * 128;

    int tid  = threadIdx.x;
    int lane = tid & 31, warp = tid >> 5;
    int wm = warp >> 1, wn = warp & 1;
    int g  = lane >> 2, tig = lane & 3;

    const float* Ag = A  + (size_t)row0 * lda;
    const float* Bg = Bm + (size_t)col0 * ldb;
    int arow = tid >> 2, ac = (tid & 3) * 4;

    float acc[4][8][4];
#pragma unroll
    for (int i = 0; i < 4; i++)
#pragma unroll
        for (int j = 0; j < 8; j++)
#pragma unroll
            for (int r = 0; r < 4; r++) acc[i][j][r] = 0.f;

    int iters = K / 16;

    {
#pragma unroll
        for (int p = 0; p < 4; p++)
            cp16(&As[0][arow + 32 * p][ac], Ag + (size_t)(arow + 32 * p) * lda + ac);
#pragma unroll
        for (int p = 0; p < 4; p++)
            cp16(&Bt[0][arow + 32 * p][ac], Bg + (size_t)(arow + 32 * p) * ldb + ac);
        cp_commit();
    }

    int cur = 0;
    for (int it = 0; it < iters; ++it) {
        bool hn = (it + 1 < iters);
        if (hn) {
            int k0 = (it + 1) * 16;
            int nxt = cur ^ 1;
#pragma unroll
            for (int p = 0; p < 4; p++)
                cp16(&As[nxt][arow + 32 * p][ac], Ag + (size_t)(arow + 32 * p) * lda + k0 + ac);
#pragma unroll
            for (int p = 0; p < 4; p++)
                cp16(&Bt[nxt][arow + 32 * p][ac], Bg + (size_t)(arow + 32 * p) * ldb + k0 + ac);
            cp_commit();
            asm volatile("cp.async.wait_group 1;\n" ::);
        } else {
            asm volatile("cp.async.wait_group 0;\n" ::);
        }
        __syncthreads();
        compute_k8_nt(As[cur], Bt[cur], acc, 0, wm, wn, g, tig);
        compute_k8_nt(As[cur], Bt[cur], acc, 8, wm, wn, g, tig);
        __syncthreads();
        cur ^= 1;
    }

#pragma unroll
    for (int mt = 0; mt < 4; mt++) {
#pragma unroll
        for (int nt = 0; nt < 8; nt++) {
            int r = row0 + wm * 64 + mt * 16 + g;
            int c = col0 + wn * 64 + nt * 8 + tig * 2;
#pragma unroll
            for (int half = 0; half < 2; half++) {
                float* p = Cm + (size_t)(r + 8 * half) * ldc + c;
                p[0] = acc[mt][nt][2*half + 0] * scale;
                p[1] = acc[mt][nt][2*half + 1] * scale;
            }
        }
    }
}

// ---------------------------------------------------------------------------
// Host launch
// ---------------------------------------------------------------------------
extern "C" void kernel_launch(void* const* d_in, const int* in_sizes, int n_in,
                              void* d_out, int out_size) {
    const int*   idx = (const int*)  d_in[0];
    const float* tok = (const float*)d_in[1];
    const float* pos = (const float*)d_in[2];
    const float* Wq  = (const float*)d_in[3];
    const float* Wk  = (const float*)d_in[4];
    const float* Wv  = (const float*)d_in[5];
    const float* Wo  = (const float*)d_in[6];
    const float* bo  = (const float*)d_in[7];
    const float* W1  = (const float*)d_in[8];
    const float* b1  = (const float*)d_in[9];
    const float* W2  = (const float*)d_in[10];
    const float* b2  = (const float*)d_in[11];
    const float* g1  = (const float*)d_in[12];
    const float* be1 = (const float*)d_in[13];
    const float* g2  = (const float*)d_in[14];
    const float* be2 = (const float*)d_in[15];
    const float* gf  = (const float*)d_in[16];
    const float* bef = (const float*)d_in[17];
    const float* Wlm = (const float*)d_in[18];
    const float* blm = (const float*)d_in[19];
    float* out = (float*)d_out;

    float *x, *h, *q, *k, *v, *att, *ffn, *wei;
    float *cWq, *cWk, *cWv, *cWo, *cW1, *cW2, *cWlm;
    cudaGetSymbolAddress((void**)&x,   g_x);
    cudaGetSymbolAddress((void**)&h,   g_h);
    cudaGetSymbolAddress((void**)&q,   g_q);
    cudaGetSymbolAddress((void**)&k,   g_k);
    cudaGetSymbolAddress((void**)&v,   g_v);
    cudaGetSymbolAddress((void**)&att, g_att);
    cudaGetSymbolAddress((void**)&ffn, g_ffn);
    cudaGetSymbolAddress((void**)&wei, g_wei);
    cudaGetSymbolAddress((void**)&cWq, g_cWq);
    cudaGetSymbolAddress((void**)&cWk, g_cWk);
    cudaGetSymbolAddress((void**)&cWv, g_cWv);
    cudaGetSymbolAddress((void**)&cWo, g_cWo);
    cudaGetSymbolAddress((void**)&cW1, g_cW1);
    cudaGetSymbolAddress((void**)&cW2, g_cW2);
    cudaGetSymbolAddress((void**)&cWlm, g_cWlm);

    // 0. pre-round weights to tf32 format
    {
        auto cvt = [](const float* in, float* outp, long n) {
            int n4 = (int)(n / 4);
            cvt_tf32_kernel<<<(n4 + 255) / 256, 256>>>((const float4*)in, (float4*)outp, n4);
        };
        cvt(Wq, cWq, (long)H_*C_*D_);
        cvt(Wk, cWk, (long)H_*C_*D_);
        cvt(Wv, cWv, (long)H_*C_*D_);
        cvt(Wo, cWo, (long)HD_*C_);
        cvt(W1, cW1, (long)C_*FF_);
        cvt(W2, cW2, (long)FF_*C_);
        cvt(Wlm, cWlm, (long)C_*V_);
    }

    // 1. embedding
    embed_kernel<<<(B_*T_*C_)/256, 256>>>(idx, tok, pos);

    // 2. LN1 (tf32-rounded output)
    ln_kernel<<<B_*T_, 256>>>(x, h, g1, be1);

    // 3. q,k,v projections (outputs rounded — they feed attention GEMMs)
    {
        dim3 grid(D_/128, T_/128, B_*H_);
        long sAb = (long)T_*C_, sBh = (long)C_*D_;
        long sCb = (long)H_*T_*D_, sCh = (long)T_*D_;
        mma_nn<<<grid, 128>>>(h, cWq, q, C_, C_, D_, D_,
                              sAb, 0, 0, sBh, sCb, sCh, H_, nullptr, 1.f, F_TF32);
        mma_nn<<<grid, 128>>>(h, cWk, k, C_, C_, D_, D_,
                              sAb, 0, 0, sBh, sCb, sCh, H_, nullptr, 1.f, F_TF32);
        mma_nn<<<grid, 128>>>(h, cWv, v, C_, C_, D_, D_,
                              sAb, 0, 0, sBh, sCb, sCh, H_, nullptr, 1.f, F_TF32);
    }

    // 4. scores
    {
        dim3 grid(T_/128, T_/128, B_*H_);
        mma_nt_scores<<<grid, 128>>>(q, k, wei, D_, D_, D_, T_,
                                     (long)T_*D_, (long)T_*D_, (long)T_*T_,
                                     rsqrtf((float)D_));
    }

    // 5. softmax (tf32-rounded probs)
    softmax_kernel<<<B_*H_*T_, 256>>>(wei);

    // 6. att = wei @ v  ([B,T,H*D] layout, causal K-limit, rounded output)
    {
        dim3 grid(D_/128, T_/128, B_*H_);
        mma_nn<<<grid, 128>>>(wei, v, att, T_, T_, D_, HD_,
                              (long)H_*T_*T_, (long)T_*T_,
                              (long)H_*T_*D_, (long)T_*D_,
                              (long)T_*HD_, (long)D_, H_,
                              nullptr, 1.f, F_CAUSALK | F_TF32);
    }

    // 7. x += att @ Wo + bo
    mma_nn<<<dim3(C_/128, (B_*T_)/128, 1), 128>>>(
        att, cWo, x, HD_, HD_, C_, C_,
        0, 0, 0, 0, 0, 0, 1, bo, 1.f, F_BIAS | F_ADDC);

    // 8. LN2
    ln_kernel<<<B_*T_, 256>>>(x, h, g2, be2);

    // 9. ffn = relu(h @ W1 + b1)  (rounded output)
    mma_nn<<<dim3(FF_/128, (B_*T_)/128, 1), 128>>>(
        h, cW1, ffn, C_, C_, FF_, FF_,
        0, 0, 0, 0, 0, 0, 1, b1, 1.f, F_BIAS | F_RELU | F_TF32);

    // 10. x += ffn @ W2 + b2
    mma_nn<<<dim3(C_/128, (B_*T_)/128, 1), 128>>>(
        ffn, cW2, x, FF_, FF_, C_, C_,
        0, 0, 0, 0, 0, 0, 1, b2, 1.f, F_BIAS | F_ADDC);

    // 11. final LN
    ln_kernel<<<B_*T_, 256>>>(x, h, gf, bef);

    // 12. logits = h @ Wlm + blm
    mma_nn<<<dim3(V_/128, (B_*T_)/128, 1), 128>>>(
        h, cWlm, out, C_, C_, V_, V_,
        0, 0, 0, 0, 0, 0, 1, blm, 1.f, F_BIAS);
}

// round 7
// speedup vs baseline: 1.1206x; 1.0654x over previous
#include <cuda_runtime.h>
#include <cuda_bf16.h>
#include <math.h>

// Problem constants
#define B_ 2
#define T_ 2048
#define C_ 1024
#define H_ 8
#define D_ 1024
#define V_ 32000
#define HD_ (H_*D_)
#define FF_ (4*C_)

// Scratch (device globals; no dynamic allocation allowed)
__device__ float g_x  [B_*T_*C_];
__device__ float g_h  [B_*T_*C_];
__device__ float g_q  [B_*H_*T_*D_];
__device__ float g_k  [B_*H_*T_*D_];
__device__ float g_v  [B_*H_*T_*D_];
__device__ float g_att[B_*T_*HD_];
__device__ float g_ffn[B_*T_*FF_];
__device__ float g_wei[(size_t)B_*H_*T_*T_];
// tf32-rounded weight copies
__device__ float g_cWq [H_*C_*D_];
__device__ float g_cWk [H_*C_*D_];
__device__ float g_cWv [H_*C_*D_];
__device__ float g_cWo [HD_*C_];
__device__ float g_cW1 [C_*FF_];
__device__ float g_cW2 [FF_*C_];
__device__ float g_cWlm[C_*V_];

#define F_BIAS    1
#define F_ADDC    2
#define F_RELU    4
#define F_CAUSALK 8
#define F_TF32    16

__device__ __forceinline__ float tf32r(float x) {
    unsigned r;
    asm("cvt.rna.tf32.f32 %0, %1;" : "=r"(r) : "f"(x));
    return __uint_as_float(r);
}

// ---------------------------------------------------------------------------
// Weight pre-rounding (float4)
// ---------------------------------------------------------------------------
__global__ void cvt_tf32_kernel(const float4* __restrict__ in, float4* __restrict__ out, int n4) {
    int i = blockIdx.x * blockDim.x + threadIdx.x;
    if (i < n4) {
        float4 v = in[i];
        v.x = tf32r(v.x); v.y = tf32r(v.y); v.z = tf32r(v.z); v.w = tf32r(v.w);
        out[i] = v;
    }
}

// ---------------------------------------------------------------------------
// Embedding
// ---------------------------------------------------------------------------
__global__ void embed_kernel(const int* __restrict__ idx,
                             const float* __restrict__ tok,
                             const float* __restrict__ pos) {
    int i = blockIdx.x * blockDim.x + threadIdx.x;
    int c  = i % C_;
    int bt = i / C_;
    int t  = bt % T_;
    g_x[i] = tok[(size_t)idx[bt] * C_ + c] + pos[t * C_ + c];
}

// ---------------------------------------------------------------------------
// LayerNorm (C=1024); output tf32-rounded (feeds GEMM operands)
// ---------------------------------------------------------------------------
__global__ void ln_kernel(const float* __restrict__ in, float* __restrict__ out,
                          const float* __restrict__ g, const float* __restrict__ b) {
    int row = blockIdx.x;
    const float* x = in + (size_t)row * C_;
    float* o = out + (size_t)row * C_;
    int tid = threadIdx.x;

    __shared__ float rs[256], rss[256];
    float s = 0.f, ss = 0.f;
    for (int c = tid; c < C_; c += 256) { float v = x[c]; s += v; ss += v * v; }
    rs[tid] = s; rss[tid] = ss;
    __syncthreads();
    for (int off = 128; off > 0; off >>= 1) {
        if (tid < off) { rs[tid] += rs[tid + off]; rss[tid] += rss[tid + off]; }
        __syncthreads();
    }
    float mean = rs[0] * (1.0f / C_);
    float var  = rss[0] * (1.0f / C_) - mean * mean;
    float inv  = rsqrtf(var + 1e-5f);
    for (int c = tid; c < C_; c += 256)
        o[c] = tf32r((x[c] - mean) * inv * g[c] + b[c]);
}

// ---------------------------------------------------------------------------
// Causal softmax; probs tf32-rounded; zero pad up to next 128 boundary
// ---------------------------------------------------------------------------
__global__ void softmax_kernel(float* __restrict__ wei) {
    int row = blockIdx.x;
    int t = row % T_;
    float* w = wei + (size_t)row * T_;
    int n = t + 1;
    int tid = threadIdx.x;
    __shared__ float red[256];

    float m = -1e30f;
    for (int s = tid; s < n; s += 256) m = fmaxf(m, w[s]);
    red[tid] = m;
    __syncthreads();
    for (int off = 128; off > 0; off >>= 1) {
        if (tid < off) red[tid] = fmaxf(red[tid], red[tid + off]);
        __syncthreads();
    }
    m = red[0];
    __syncthreads();

    float sum = 0.f;
    for (int s = tid; s < n; s += 256) { float e = expf(w[s] - m); w[s] = e; sum += e; }
    red[tid] = sum;
    __syncthreads();
    for (int off = 128; off > 0; off >>= 1) {
        if (tid < off) red[tid] += red[tid + off];
        __syncthreads();
    }
    float inv = 1.f / red[0];
    for (int s = tid; s < n; s += 256) w[s] = tf32r(w[s] * inv);

    int nend = (n + 127) & ~127;
    for (int s = n + tid; s < nend; s += 256) w[s] = 0.f;
}

// ---------------------------------------------------------------------------
// mma helpers (operands pre-rounded to tf32 — no cvt in loop)
// ---------------------------------------------------------------------------
__device__ __forceinline__ void mma8(float* d, const unsigned* a, unsigned b0, unsigned b1) {
    asm volatile(
        "mma.sync.aligned.m16n8k8.row.col.f32.tf32.tf32.f32 "
        "{%0,%1,%2,%3}, {%4,%5,%6,%7}, {%8,%9}, {%0,%1,%2,%3};\n"
        : "+f"(d[0]), "+f"(d[1]), "+f"(d[2]), "+f"(d[3])
        : "r"(a[0]), "r"(a[1]), "r"(a[2]), "r"(a[3]), "r"(b0), "r"(b1));
}

__device__ __forceinline__ void cp16(void* s, const void* g) {
    unsigned sa = (unsigned)__cvta_generic_to_shared(s);
    asm volatile("cp.async.cg.shared.global [%0], [%1], 16;\n" :: "r"(sa), "l"(g));
}
__device__ __forceinline__ void cp_commit() {
    asm volatile("cp.async.commit_group;\n" ::);
}
__device__ __forceinline__ unsigned ldu(const float* p) {
    return __float_as_uint(*p);
}

// A-style tile: [128 rows][k, stride 20]  (banks 20g+tig -> conflict-free)
// B-style tile: [16 k-rows][col, stride 136] (banks 8tig+g -> conflict-free)
#define AP 20
#define BP 136
#define A_W (128*AP)       // floats per A stage (2560)
#define B_W (16*BP)        // floats per B stage (2176)
#define STG_NN (A_W + B_W) // 4736 floats = 18944 B
#define STG_NT (A_W + A_W) // 5120 floats = 20480 B
#define SMEM_NN (3*STG_NN*4)
#define SMEM_NT (3*STG_NT*4)

// Warp tile 64x64: 4 m-subtiles x 8 n-subtiles
__device__ __forceinline__ void compute_k8_nn(
    const float (* __restrict__ As)[AP], const float (* __restrict__ Bs)[BP],
    float acc[4][8][4], int kk, int wm, int wn, int g, int tig)
{
    unsigned a[4][4];
#pragma unroll
    for (int mt = 0; mt < 4; mt++) {
        int mrow = wm * 64 + mt * 16;
        a[mt][0] = ldu(&As[mrow + g    ][kk + tig    ]);
        a[mt][1] = ldu(&As[mrow + g + 8][kk + tig    ]);
        a[mt][2] = ldu(&As[mrow + g    ][kk + tig + 4]);
        a[mt][3] = ldu(&As[mrow + g + 8][kk + tig + 4]);
    }
#pragma unroll
    for (int nt = 0; nt < 8; nt++) {
        int ncol = wn * 64 + nt * 8 + g;
        unsigned b0 = ldu(&Bs[kk + tig    ][ncol]);
        unsigned b1 = ldu(&Bs[kk + tig + 4][ncol]);
#pragma unroll
        for (int mt = 0; mt < 4; mt++) mma8(acc[mt][nt], a[mt], b0, b1);
    }
}

__device__ __forceinline__ void compute_k8_nt(
    const float (* __restrict__ As)[AP], const float (* __restrict__ Bt)[AP],
    float acc[4][8][4], int kk, int wm, int wn, int g, int tig)
{
    unsigned a[4][4];
#pragma unroll
    for (int mt = 0; mt < 4; mt++) {
        int mrow = wm * 64 + mt * 16;
        a[mt][0] = ldu(&As[mrow + g    ][kk + tig    ]);
        a[mt][1] = ldu(&As[mrow + g + 8][kk + tig    ]);
        a[mt][2] = ldu(&As[mrow + g    ][kk + tig + 4]);
        a[mt][3] = ldu(&As[mrow + g + 8][kk + tig + 4]);
    }
#pragma unroll
    for (int nt = 0; nt < 8; nt++) {
        int ncol = wn * 64 + nt * 8 + g;
        unsigned b0 = ldu(&Bt[ncol][kk + tig    ]);
        unsigned b1 = ldu(&Bt[ncol][kk + tig + 4]);
#pragma unroll
        for (int mt = 0; mt < 4; mt++) mma8(acc[mt][nt], a[mt], b0, b1);
    }
}

// ---------------------------------------------------------------------------
// tf32 GEMM NN: 128x128 tile, BK=16, 128 threads, 3-stage ring, 1 sync/iter
// ---------------------------------------------------------------------------
__global__ void __launch_bounds__(128, 2)
mma_nn(const float* __restrict__ A, const float* __restrict__ Bm,
       float* __restrict__ Cm,
       int K, int lda, int ldb, int ldc,
       long sAb, long sAh, long sBb, long sBh, long sCb, long sCh, int batchH,
       const float* __restrict__ bias, float scale, int flags)
{
    extern __shared__ float dsm[];

    int z  = blockIdx.z;
    int zb = z / batchH, zh = z % batchH;
    A  += zb * sAb + zh * sAh;
    Bm += zb * sBb + zh * sBh;
    Cm += zb * sCb + zh * sCh;

    int bx = blockIdx.x, by = blockIdx.y;
    int row0 = by * 128, col0 = bx * 128;

    int Keff = K;
    if (flags & F_CAUSALK) { int kl = (by + 1) * 128; if (kl < Keff) Keff = kl; }

    int tid  = threadIdx.x;
    int lane = tid & 31, warp = tid >> 5;
    int wm = warp >> 1, wn = warp & 1;
    int g  = lane >> 2, tig = lane & 3;

    const float* Ag = A  + (size_t)row0 * lda;
    const float* Bg = Bm + col0;
    int arow = tid >> 2, ac = (tid & 3) * 4;   // A: 32 rows x 16k per pass
    int brow = tid >> 5, bc = (tid & 31) * 4;  // B: 4 k-rows x 128 cols per pass

    float acc[4][8][4];
#pragma unroll
    for (int i = 0; i < 4; i++)
#pragma unroll
        for (int j = 0; j < 8; j++)
#pragma unroll
            for (int r = 0; r < 4; r++) acc[i][j][r] = 0.f;

    int iters = Keff / 16;

    // prologue: stages 0 and 1
#pragma unroll
    for (int st = 0; st < 2; st++) {
        if (st < iters) {
            float* As = dsm + st * STG_NN;
            float* Bs = As + A_W;
            int k0 = st * 16;
#pragma unroll
            for (int p = 0; p < 4; p++)
                cp16(&As[(arow + 32 * p) * AP + ac], Ag + (size_t)(arow + 32 * p) * lda + k0 + ac);
#pragma unroll
            for (int p = 0; p < 4; p++)
                cp16(&Bs[(brow + 4 * p) * BP + bc], Bg + (size_t)(k0 + brow + 4 * p) * ldb + bc);
            cp_commit();
        }
    }

    for (int it = 0; it < iters; ++it) {
        if (it + 1 < iters) asm volatile("cp.async.wait_group 1;\n" ::);
        else                asm volatile("cp.async.wait_group 0;\n" ::);
        __syncthreads();
        if (it + 2 < iters) {
            int st = (it + 2) % 3;
            int k0 = (it + 2) * 16;
            float* As = dsm + st * STG_NN;
            float* Bs = As + A_W;
#pragma unroll
            for (int p = 0; p < 4; p++)
                cp16(&As[(arow + 32 * p) * AP + ac], Ag + (size_t)(arow + 32 * p) * lda + k0 + ac);
#pragma unroll
            for (int p = 0; p < 4; p++)
                cp16(&Bs[(brow + 4 * p) * BP + bc], Bg + (size_t)(k0 + brow + 4 * p) * ldb + bc);
            cp_commit();
        }
        const float (*As)[AP] = (const float (*)[AP])(dsm + (it % 3) * STG_NN);
        const float (*Bs)[BP] = (const float (*)[BP])(dsm + (it % 3) * STG_NN + A_W);
        compute_k8_nn(As, Bs, acc, 0, wm, wn, g, tig);
        compute_k8_nn(As, Bs, acc, 8, wm, wn, g, tig);
    }

    // epilogue
#pragma unroll
    for (int mt = 0; mt < 4; mt++) {
#pragma unroll
        for (int nt = 0; nt < 8; nt++) {
            int r = row0 + wm * 64 + mt * 16 + g;
            int c = col0 + wn * 64 + nt * 8 + tig * 2;
#pragma unroll
            for (int half = 0; half < 2; half++) {
                float* p = Cm + (size_t)(r + 8 * half) * ldc + c;
                float x0 = acc[mt][nt][2*half + 0] * scale;
                float x1 = acc[mt][nt][2*half + 1] * scale;
                if (flags & F_BIAS) { x0 += bias[c]; x1 += bias[c + 1]; }
                if (flags & F_RELU) { x0 = fmaxf(x0, 0.f); x1 = fmaxf(x1, 0.f); }
                if (flags & F_TF32) { x0 = tf32r(x0); x1 = tf32r(x1); }
                if (flags & F_ADDC) { x0 += p[0]; x1 += p[1]; }
                p[0] = x0; p[1] = x1;
            }
        }
    }
}

// ---------------------------------------------------------------------------
// tf32 GEMM NT (scores): C = scale * A[M,K] @ B[N,K]^T, causal tile skip
// ---------------------------------------------------------------------------
__global__ void __launch_bounds__(128, 2)
mma_nt_scores(const float* __restrict__ A, const float* __restrict__ Bm,
              float* __restrict__ Cm,
              int K, int lda, int ldb, int ldc,
              long sA, long sB, long sC, float scale)
{
    int bx = blockIdx.x, by = blockIdx.y;
    if (bx > by) return;

    extern __shared__ float dsm[];

    int z = blockIdx.z;
    A  += (long)z * sA;
    Bm += (long)z * sB;
    Cm += (long)z * sC;

    int row0 = by * 128, col0 = bx * 128;

    int tid  = threadIdx.x;
    int lane = tid & 31, warp = tid >> 5;
    int wm = warp >> 1, wn = warp & 1;
    int g  = lane >> 2, tig = lane & 3;

    const float* Ag = A  + (size_t)row0 * lda;
    const float* Bg = Bm + (size_t)col0 * ldb;
    int arow = tid >> 2, ac = (tid & 3) * 4;

    float acc[4][8][4];
#pragma unroll
    for (int i = 0; i < 4; i++)
#pragma unroll
        for (int j = 0; j < 8; j++)
#pragma unroll
            for (int r = 0; r < 4; r++) acc[i][j][r] = 0.f;

    int iters = K / 16;

    // prologue: stages 0 and 1
#pragma unroll
    for (int st = 0; st < 2; st++) {
        if (st < iters) {
            float* As = dsm + st * STG_NT;
            float* Bt = As + A_W;
            int k0 = st * 16;
#pragma unroll
            for (int p = 0; p < 4; p++)
                cp16(&As[(arow + 32 * p) * AP + ac], Ag + (size_t)(arow + 32 * p) * lda + k0 + ac);
#pragma unroll
            for (int p = 0; p < 4; p++)
                cp16(&Bt[(arow + 32 * p) * AP + ac], Bg + (size_t)(arow + 32 * p) * ldb + k0 + ac);
            cp_commit();
        }
    }

    for (int it = 0; it < iters; ++it) {
        if (it + 1 < iters) asm volatile("cp.async.wait_group 1;\n" ::);
        else                asm volatile("cp.async.wait_group 0;\n" ::);
        __syncthreads();
        if (it + 2 < iters) {
            int st = (it + 2) % 3;
            int k0 = (it + 2) * 16;
            float* As = dsm + st * STG_NT;
            float* Bt = As + A_W;
#pragma unroll
            for (int p = 0; p < 4; p++)
                cp16(&As[(arow + 32 * p) * AP + ac], Ag + (size_t)(arow + 32 * p) * lda + k0 + ac);
#pragma unroll
            for (int p = 0; p < 4; p++)
                cp16(&Bt[(arow + 32 * p) * AP + ac], Bg + (size_t)(arow + 32 * p) * ldb + k0 + ac);
            cp_commit();
        }
        const float (*As)[AP] = (const float (*)[AP])(dsm + (it % 3) * STG_NT);
        const float (*Bt)[AP] = (const float (*)[AP])(dsm + (it % 3) * STG_NT + A_W);
        compute_k8_nt(As, Bt, acc, 0, wm, wn, g, tig);
        compute_k8_nt(As, Bt, acc, 8, wm, wn, g, tig);
    }

#pragma unroll
    for (int mt = 0; mt < 4; mt++) {
#pragma unroll
        for (int nt = 0; nt < 8; nt++) {
            int r = row0 + wm * 64 + mt * 16 + g;
            int c = col0 + wn * 64 + nt * 8 + tig * 2;
#pragma unroll
            for (int half = 0; half < 2; half++) {
                float* p = Cm + (size_t)(r + 8 * half) * ldc + c;
                p[0] = acc[mt][nt][2*half + 0] * scale;
                p[1] = acc[mt][nt][2*half + 1] * scale;
            }
        }
    }
}

// ---------------------------------------------------------------------------
// Host launch
// ---------------------------------------------------------------------------
extern "C" void kernel_launch(void* const* d_in, const int* in_sizes, int n_in,
                              void* d_out, int out_size) {
    const int*   idx = (const int*)  d_in[0];
    const float* tok = (const float*)d_in[1];
    const float* pos = (const float*)d_in[2];
    const float* Wq  = (const float*)d_in[3];
    const float* Wk  = (const float*)d_in[4];
    const float* Wv  = (const float*)d_in[5];
    const float* Wo  = (const float*)d_in[6];
    const float* bo  = (const float*)d_in[7];
    const float* W1  = (const float*)d_in[8];
    const float* b1  = (const float*)d_in[9];
    const float* W2  = (const float*)d_in[10];
    const float* b2  = (const float*)d_in[11];
    const float* g1  = (const float*)d_in[12];
    const float* be1 = (const float*)d_in[13];
    const float* g2  = (const float*)d_in[14];
    const float* be2 = (const float*)d_in[15];
    const float* gf  = (const float*)d_in[16];
    const float* bef = (const float*)d_in[17];
    const float* Wlm = (const float*)d_in[18];
    const float* blm = (const float*)d_in[19];
    float* out = (float*)d_out;

    float *x, *h, *q, *k, *v, *att, *ffn, *wei;
    float *cWq, *cWk, *cWv, *cWo, *cW1, *cW2, *cWlm;
    cudaGetSymbolAddress((void**)&x,   g_x);
    cudaGetSymbolAddress((void**)&h,   g_h);
    cudaGetSymbolAddress((void**)&q,   g_q);
    cudaGetSymbolAddress((void**)&k,   g_k);
    cudaGetSymbolAddress((void**)&v,   g_v);
    cudaGetSymbolAddress((void**)&att, g_att);
    cudaGetSymbolAddress((void**)&ffn, g_ffn);
    cudaGetSymbolAddress((void**)&wei, g_wei);
    cudaGetSymbolAddress((void**)&cWq, g_cWq);
    cudaGetSymbolAddress((void**)&cWk, g_cWk);
    cudaGetSymbolAddress((void**)&cWv, g_cWv);
    cudaGetSymbolAddress((void**)&cWo, g_cWo);
    cudaGetSymbolAddress((void**)&cW1, g_cW1);
    cudaGetSymbolAddress((void**)&cW2, g_cW2);
    cudaGetSymbolAddress((void**)&cWlm, g_cWlm);

    cudaFuncSetAttribute(mma_nn,        cudaFuncAttributeMaxDynamicSharedMemorySize, SMEM_NN);
    cudaFuncSetAttribute(mma_nt_scores, cudaFuncAttributeMaxDynamicSharedMemorySize, SMEM_NT);

    // 0. pre-round weights to tf32 format
    {
        auto cvt = [](const float* in, float* outp, long n) {
            int n4 = (int)(n / 4);
            cvt_tf32_kernel<<<(n4 + 255) / 256, 256>>>((const float4*)in, (float4*)outp, n4);
        };
        cvt(Wq, cWq, (long)H_*C_*D_);
        cvt(Wk, cWk, (long)H_*C_*D_);
        cvt(Wv, cWv, (long)H_*C_*D_);
        cvt(Wo, cWo, (long)HD_*C_);
        cvt(W1, cW1, (long)C_*FF_);
        cvt(W2, cW2, (long)FF_*C_);
        cvt(Wlm, cWlm, (long)C_*V_);
    }

    // 1. embedding
    embed_kernel<<<(B_*T_*C_)/256, 256>>>(idx, tok, pos);

    // 2. LN1
    ln_kernel<<<B_*T_, 256>>>(x, h, g1, be1);

    // 3. q,k,v projections
    {
        dim3 grid(D_/128, T_/128, B_*H_);
        long sAb = (long)T_*C_, sBh = (long)C_*D_;
        long sCb = (long)H_*T_*D_, sCh = (long)T_*D_;
        mma_nn<<<grid, 128, SMEM_NN>>>(h, cWq, q, C_, C_, D_, D_,
                              sAb, 0, 0, sBh, sCb, sCh, H_, nullptr, 1.f, F_TF32);
        mma_nn<<<grid, 128, SMEM_NN>>>(h, cWk, k, C_, C_, D_, D_,
                              sAb, 0, 0, sBh, sCb, sCh, H_, nullptr, 1.f, F_TF32);
        mma_nn<<<grid, 128, SMEM_NN>>>(h, cWv, v, C_, C_, D_, D_,
                              sAb, 0, 0, sBh, sCb, sCh, H_, nullptr, 1.f, F_TF32);
    }

    // 4. scores
    {
        dim3 grid(T_/128, T_/128, B_*H_);
        mma_nt_scores<<<grid, 128, SMEM_NT>>>(q, k, wei, D_, D_, D_, T_,
                                     (long)T_*D_, (long)T_*D_, (long)T_*T_,
                                     rsqrtf((float)D_));
    }

    // 5. softmax
    softmax_kernel<<<B_*H_*T_, 256>>>(wei);

    // 6. att = wei @ v  ([B,T,H*D] layout, causal K-limit)
    {
        dim3 grid(D_/128, T_/128, B_*H_);
        mma_nn<<<grid, 128, SMEM_NN>>>(wei, v, att, T_, T_, D_, HD_,
                              (long)H_*T_*T_, (long)T_*T_,
                              (long)H_*T_*D_, (long)T_*D_,
                              (long)T_*HD_, (long)D_, H_,
                              nullptr, 1.f, F_CAUSALK | F_TF32);
    }

    // 7. x += att @ Wo + bo
    mma_nn<<<dim3(C_/128, (B_*T_)/128, 1), 128, SMEM_NN>>>(
        att, cWo, x, HD_, HD_, C_, C_,
        0, 0, 0, 0, 0, 0, 1, bo, 1.f, F_BIAS | F_ADDC);

    // 8. LN2
    ln_kernel<<<B_*T_, 256>>>(x, h, g2, be2);

    // 9. ffn = relu(h @ W1 + b1)
    mma_nn<<<dim3(FF_/128, (B_*T_)/128, 1), 128, SMEM_NN>>>(
        h, cW1, ffn, C_, C_, FF_, FF_,
        0, 0, 0, 0, 0, 0, 1, b1, 1.f, F_BIAS | F_RELU | F_TF32);

    // 10. x += ffn @ W2 + b2
    mma_nn<<<dim3(C_/128, (B_*T_)/128, 1), 128, SMEM_NN>>>(
        ffn, cW2, x, FF_, FF_, C_, C_,
        0, 0, 0, 0, 0, 0, 1, b2, 1.f, F_BIAS | F_ADDC);

    // 11. final LN
    ln_kernel<<<B_*T_, 256>>>(x, h, gf, bef);

    // 12. logits = h @ Wlm + blm
    mma_nn<<<dim3(V_/128, (B_*T_)/128, 1), 128, SMEM_NN>>>(
        h, cWlm, out, C_, C_, V_, V_,
        0, 0, 0, 0, 0, 0, 1, blm, 1.f, F_BIAS);
}